// round 1
// baseline (speedup 1.0000x reference)
#include <cuda_runtime.h>
#include <cstdint>

// Problem constants
#define NB    4
#define NSEQ  4096          // 64*64 tokens per batch
#define NTOK  (NB*NSEQ)     // 16384
#define DQK   32
#define CF    256

// Scratch (device globals: no allocation allowed in kernel_launch)
__device__ float g_q[NTOK * DQK];
__device__ float g_k[NTOK * DQK];
__device__ float g_v[(size_t)NTOK * CF];
__device__ float g_att[(size_t)NTOK * CF];

// ---------------------------------------------------------------------------
// packed f32x2 helpers (FFMA2: 2 fp32 FMAs per issue slot on sm_103a)
// ---------------------------------------------------------------------------
__device__ __forceinline__ void fma2(unsigned long long& a,
                                     unsigned long long v,
                                     unsigned long long p) {
    asm("fma.rn.f32x2 %0, %1, %2, %0;" : "+l"(a) : "l"(v), "l"(p));
}
__device__ __forceinline__ unsigned long long pack2(float x) {
    unsigned long long r;
    asm("mov.b64 %0, {%1, %1};" : "=l"(r) : "f"(x));
    return r;
}
__device__ __forceinline__ float2 unpack2(unsigned long long u) {
    float2 f;
    asm("mov.b64 {%0, %1}, %2;" : "=f"(f.x), "=f"(f.y) : "l"(u));
    return f;
}

// ---------------------------------------------------------------------------
// GEMM: C[16384, Ncols] = relu(A[16384,256] @ W[256,Ncols] + bias) (+ residual)
// BM=64, BN=64, BK=16, 256 threads, 4x4 microtile per thread.
// ---------------------------------------------------------------------------
template<int RES>
__global__ void __launch_bounds__(256)
gemm_relu_kernel(const float* __restrict__ A, const float* __restrict__ W,
                 const float* __restrict__ bias, const float* __restrict__ res,
                 float* __restrict__ C, int Ncols) {
    __shared__ float As[16][68];   // transposed: As[k][m]
    __shared__ float Ws[16][68];   // Ws[k][n]

    const int t  = threadIdx.x;
    const int m0 = blockIdx.y * 64;
    const int n0 = blockIdx.x * 64;
    const int r0 = (t >> 4) * 4;
    const int c0 = (t & 15) * 4;

    float acc[4][4] = {};

    for (int k0 = 0; k0 < 256; k0 += 16) {
        // A tile (64x16) -> transposed smem
        {
            int m  = t >> 2;
            int kg = (t & 3) * 4;
            float4 a = *(const float4*)(A + (size_t)(m0 + m) * 256 + k0 + kg);
            As[kg + 0][m] = a.x;
            As[kg + 1][m] = a.y;
            As[kg + 2][m] = a.z;
            As[kg + 3][m] = a.w;
        }
        // W tile (16x64), column-guarded for Ncols=32
        {
            int kk = t >> 4;
            int n  = (t & 15) * 4;
#pragma unroll
            for (int j = 0; j < 4; ++j) {
                int col = n0 + n + j;
                Ws[kk][n + j] = (col < Ncols)
                              ? W[(size_t)(k0 + kk) * Ncols + col] : 0.f;
            }
        }
        __syncthreads();

#pragma unroll
        for (int kk = 0; kk < 16; ++kk) {
            float4 a = *(const float4*)&As[kk][r0];
            float4 w = *(const float4*)&Ws[kk][c0];
            float av[4] = {a.x, a.y, a.z, a.w};
            float wv[4] = {w.x, w.y, w.z, w.w};
#pragma unroll
            for (int i = 0; i < 4; ++i)
#pragma unroll
                for (int j = 0; j < 4; ++j)
                    acc[i][j] += av[i] * wv[j];
        }
        __syncthreads();
    }

#pragma unroll
    for (int i = 0; i < 4; ++i) {
        int m = m0 + r0 + i;
#pragma unroll
        for (int j = 0; j < 4; ++j) {
            int col = n0 + c0 + j;
            if (col < Ncols) {
                float v = fmaxf(acc[i][j] + bias[col], 0.f);
                if (RES) v += res[(size_t)m * Ncols + col];
                C[(size_t)m * Ncols + col] = v;
            }
        }
    }
}

// ---------------------------------------------------------------------------
// Attention: per CTA, 64 queries vs all 4096 keys (one batch).
// q,k,v >= 0 (post-ReLU) => logits in [0, ~25]; exp() is safe without max
// subtraction. Accumulate unnormalized O + rowsum, normalize at the end.
//
// Thread layout: row = t>>2 (one O row per 4 threads), quad lane owns columns
// c = qlane*4 + 16*j + {0..3}, j=0..15  (64 fp32 outputs = 32 f32x2 regs).
// ---------------------------------------------------------------------------
#define SQ_OFF 0
#define SK_OFF 2112               // 64*33
#define SP_OFF 4224               // + 64*33
#define SV_OFF 8384               // + 64*65
#define SMEM_FLOATS (8384 + 64*260)
#define ATTN_SMEM_BYTES (SMEM_FLOATS * 4)   // 100096 B

__global__ void __launch_bounds__(256, 2)
attn_kernel(const float* __restrict__ gq, const float* __restrict__ gk,
            const float* __restrict__ gv, float* __restrict__ gatt) {
    extern __shared__ float sm[];
    float* sQ = sm + SQ_OFF;      // [64][33]
    float* sK = sm + SK_OFF;      // [64][33]
    float* sP = sm + SP_OFF;      // [64][65]
    float* sV = sm + SV_OFF;      // [64][260]

    const int t     = threadIdx.x;
    const int b     = blockIdx.y;
    const int qt    = blockIdx.x;
    const int row   = t >> 2;     // 0..63
    const int qlane = t & 3;

    const float* qbase = gq + (size_t)(b * NSEQ + qt * 64) * DQK;
    const float* kbase = gk + (size_t)b * NSEQ * DQK;
    const float* vbase = gv + (size_t)b * NSEQ * CF;

    // Load Q tile [64][32]
    {
        int i = t;
#pragma unroll
        for (int it = 0; it < 2; ++it, i += 256) {
            int r  = i >> 3;
            int c4 = (i & 7) * 4;
            float4 v = *(const float4*)(qbase + r * DQK + c4);
            float* d = sQ + r * 33 + c4;
            d[0] = v.x; d[1] = v.y; d[2] = v.z; d[3] = v.w;
        }
    }

    unsigned long long acc[32];
#pragma unroll
    for (int i = 0; i < 32; ++i) acc[i] = 0ULL;
    float rowsum = 0.f;

    for (int kt = 0; kt < NSEQ / 64; ++kt) {
        __syncthreads();   // previous tile's P/V reads done
        // K tile [64][32]
        {
            int i = t;
#pragma unroll
            for (int it = 0; it < 2; ++it, i += 256) {
                int r  = i >> 3;
                int c4 = (i & 7) * 4;
                float4 v = *(const float4*)(kbase + (size_t)(kt * 64 + r) * DQK + c4);
                float* d = sK + r * 33 + c4;
                d[0] = v.x; d[1] = v.y; d[2] = v.z; d[3] = v.w;
            }
        }
        // V tile [64][256]
        {
            int i = t;
#pragma unroll
            for (int it = 0; it < 16; ++it, i += 256) {
                int r  = i >> 6;
                int c4 = (i & 63) * 4;
                float4 v = *(const float4*)(vbase + (size_t)(kt * 64 + r) * CF + c4);
                float* d = sV + r * 260 + c4;
                d[0] = v.x; d[1] = v.y; d[2] = v.z; d[3] = v.w;
            }
        }
        __syncthreads();

        // P = exp(Q K^T), 16 scores per thread (row fixed, kk = qlane + 4*jj)
        float psum = 0.f;
        const float* qr = sQ + row * 33;
#pragma unroll
        for (int jj = 0; jj < 16; ++jj) {
            int kk = qlane + jj * 4;
            const float* kr = sK + kk * 33;
            float s = 0.f;
#pragma unroll
            for (int d = 0; d < 32; ++d) s += qr[d] * kr[d];
            float p = __expf(s);
            sP[row * 65 + kk] = p;
            psum += p;
        }
        rowsum += psum;
        __syncthreads();

        // O += P @ V  (f32x2 packed FMAs)
#pragma unroll 4
        for (int kk = 0; kk < 64; ++kk) {
            unsigned long long p2 = pack2(sP[row * 65 + kk]);
            const ulonglong2* vp =
                (const ulonglong2*)(sV + kk * 260 + qlane * 4);
#pragma unroll
            for (int j = 0; j < 16; ++j) {
                ulonglong2 vv = vp[j * 4];   // 16 floats = 4 ulonglong2 stride
                fma2(acc[2 * j + 0], vv.x, p2);
                fma2(acc[2 * j + 1], vv.y, p2);
            }
        }
    }

    // rowsum reduce across the 4 threads of this row
    rowsum += __shfl_xor_sync(0xffffffffu, rowsum, 1);
    rowsum += __shfl_xor_sync(0xffffffffu, rowsum, 2);
    float inv = 1.f / rowsum;

    float* orow = gatt + (size_t)(b * NSEQ + qt * 64 + row) * CF;
#pragma unroll
    for (int j = 0; j < 16; ++j) {
        float2 a0 = unpack2(acc[2 * j + 0]);
        float2 a1 = unpack2(acc[2 * j + 1]);
        float4 o;
        o.x = a0.x * inv; o.y = a0.y * inv;
        o.z = a1.x * inv; o.w = a1.y * inv;
        *(float4*)(orow + qlane * 4 + 16 * j) = o;
    }
}

// ---------------------------------------------------------------------------
extern "C" void kernel_launch(void* const* d_in, const int* in_sizes, int n_in,
                              void* d_out, int out_size) {
    const float* x  = (const float*)d_in[0];
    const float* Wq = (const float*)d_in[1];
    const float* bq = (const float*)d_in[2];
    const float* Wk = (const float*)d_in[3];
    const float* bk = (const float*)d_in[4];
    const float* Wv = (const float*)d_in[5];
    const float* bv = (const float*)d_in[6];
    const float* Wo = (const float*)d_in[7];
    const float* bo = (const float*)d_in[8];
    float* out = (float*)d_out;

    void *qp, *kp, *vp, *ap;
    cudaGetSymbolAddress(&qp, g_q);
    cudaGetSymbolAddress(&kp, g_k);
    cudaGetSymbolAddress(&vp, g_v);
    cudaGetSymbolAddress(&ap, g_att);
    float* q   = (float*)qp;
    float* k   = (float*)kp;
    float* v   = (float*)vp;
    float* att = (float*)ap;

    cudaFuncSetAttribute(attn_kernel,
                         cudaFuncAttributeMaxDynamicSharedMemorySize,
                         ATTN_SMEM_BYTES);

    dim3 blk(256);
    // QKV projections
    gemm_relu_kernel<0><<<dim3(1, NTOK / 64), blk>>>(x, Wq, bq, nullptr, q, DQK);
    gemm_relu_kernel<0><<<dim3(1, NTOK / 64), blk>>>(x, Wk, bk, nullptr, k, DQK);
    gemm_relu_kernel<0><<<dim3(4, NTOK / 64), blk>>>(x, Wv, bv, nullptr, v, CF);
    // Attention
    attn_kernel<<<dim3(NSEQ / 64, NB), blk, ATTN_SMEM_BYTES>>>(q, k, v, att);
    // Output projection + residual
    gemm_relu_kernel<1><<<dim3(4, NTOK / 64), blk>>>(att, Wo, bo, x, out, CF);
}

// round 4
// speedup vs baseline: 2.5018x; 2.5018x over previous
#include <cuda_runtime.h>
#include <cstdint>

// Problem constants
#define NB    4
#define NSEQ  4096          // 64*64 tokens per batch
#define NTOK  (NB*NSEQ)     // 16384
#define DQK   32
#define CF    256

// Scratch (device globals: no allocation allowed in kernel_launch)
__device__ float g_q[NTOK * DQK];
__device__ float g_k[NTOK * DQK];
__device__ float g_v[(size_t)NTOK * CF];
__device__ float g_att[(size_t)NTOK * CF];

typedef unsigned long long ull;

// ---------------------------------------------------------------------------
// packed f32x2 helpers (FFMA2: 2 fp32 FMAs per issue slot on sm_103a)
// ---------------------------------------------------------------------------
__device__ __forceinline__ void fma2(ull& a, ull v, ull p) {
    asm("fma.rn.f32x2 %0, %1, %2, %0;" : "+l"(a) : "l"(v), "l"(p));
}
__device__ __forceinline__ ull add2(ull a, ull b) {
    ull r;
    asm("add.rn.f32x2 %0, %1, %2;" : "=l"(r) : "l"(a), "l"(b));
    return r;
}
__device__ __forceinline__ ull pack2(float x) {
    ull r;
    asm("mov.b64 %0, {%1, %1};" : "=l"(r) : "f"(x));
    return r;
}
__device__ __forceinline__ ull pack2f(float x, float y) {
    ull r;
    asm("mov.b64 %0, {%1, %2};" : "=l"(r) : "f"(x), "f"(y));
    return r;
}
__device__ __forceinline__ float2 unpack2(ull u) {
    float2 f;
    asm("mov.b64 {%0, %1}, %2;" : "=f"(f.x), "=f"(f.y) : "l"(u));
    return f;
}

// ---------------------------------------------------------------------------
// GEMM: C[16384, Ncols] = relu(A[16384,256] @ W[256,Ncols] + bias) (+ residual)
// BM=64, BN=64, BK=16, 256 threads, 4x4 microtile per thread. (unchanged, passing)
// ---------------------------------------------------------------------------
template<int RES>
__global__ void __launch_bounds__(256)
gemm_relu_kernel(const float* __restrict__ A, const float* __restrict__ W,
                 const float* __restrict__ bias, const float* __restrict__ res,
                 float* __restrict__ C, int Ncols) {
    __shared__ float As[16][68];   // transposed: As[k][m]
    __shared__ float Ws[16][68];   // Ws[k][n]

    const int t  = threadIdx.x;
    const int m0 = blockIdx.y * 64;
    const int n0 = blockIdx.x * 64;
    const int r0 = (t >> 4) * 4;
    const int c0 = (t & 15) * 4;

    float acc[4][4] = {};

    for (int k0 = 0; k0 < 256; k0 += 16) {
        {
            int m  = t >> 2;
            int kg = (t & 3) * 4;
            float4 a = *(const float4*)(A + (size_t)(m0 + m) * 256 + k0 + kg);
            As[kg + 0][m] = a.x;
            As[kg + 1][m] = a.y;
            As[kg + 2][m] = a.z;
            As[kg + 3][m] = a.w;
        }
        {
            int kk = t >> 4;
            int n  = (t & 15) * 4;
#pragma unroll
            for (int j = 0; j < 4; ++j) {
                int col = n0 + n + j;
                Ws[kk][n + j] = (col < Ncols)
                              ? W[(size_t)(k0 + kk) * Ncols + col] : 0.f;
            }
        }
        __syncthreads();

#pragma unroll
        for (int kk = 0; kk < 16; ++kk) {
            float4 a = *(const float4*)&As[kk][r0];
            float4 w = *(const float4*)&Ws[kk][c0];
            float av[4] = {a.x, a.y, a.z, a.w};
            float wv[4] = {w.x, w.y, w.z, w.w};
#pragma unroll
            for (int i = 0; i < 4; ++i)
#pragma unroll
                for (int j = 0; j < 4; ++j)
                    acc[i][j] += av[i] * wv[j];
        }
        __syncthreads();
    }

#pragma unroll
    for (int i = 0; i < 4; ++i) {
        int m = m0 + r0 + i;
#pragma unroll
        for (int j = 0; j < 4; ++j) {
            int col = n0 + c0 + j;
            if (col < Ncols) {
                float v = fmaxf(acc[i][j] + bias[col], 0.f);
                if (RES) v += res[(size_t)m * Ncols + col];
                C[(size_t)m * Ncols + col] = v;
            }
        }
    }
}

// ---------------------------------------------------------------------------
// Attention v2: register-blocked 8x8 micro-tiles.
//
// CTA = 64 queries x full key sequence (one batch). 256 threads:
//   tr = t>>5 (0..7)  -> owns query rows r0..r0+7, r0 = 8*tr  (warp == tr)
//   tc = t&31 (0..31) -> owns O columns {4tc..4tc+3} u {128+4tc..+3}
//
// Per kk in PV: V via 2 conflict-free LDS.128, P (8 rows) via 2 broadcast
// LDS.128 from transposed P; 32 fma2. Accumulators are f32x2 row-pairs.
// q,k,v >= 0 => logits bounded (~<25); exp without max subtraction;
// normalize by accumulated row sums once at the end.
// ---------------------------------------------------------------------------
#define S_Q 66
#define S_K 66
#define S_P 68
#define S_V 260
#define OFF_Q 0
#define OFF_K (32*S_Q)                 // 2112
#define OFF_P (OFF_K + 32*S_K)        // 4224
#define OFF_V (OFF_P + 64*S_P)        // 8576
#define SMEM_FLOATS (OFF_V + 64*S_V)  // 25216
#define ATTN_SMEM_BYTES (SMEM_FLOATS * 4)   // 100864 B

__global__ void __launch_bounds__(256, 2)
attn_kernel(const float* __restrict__ gq, const float* __restrict__ gk,
            const float* __restrict__ gv, float* __restrict__ gatt) {
    extern __shared__ float sm[];
    float* sQt = sm + OFF_Q;      // [32 d][64 r], stride 66
    float* sKt = sm + OFF_K;      // [32 d][64 kk], stride 66
    float* sPt = sm + OFF_P;      // [64 kk][64 r], stride 68
    float* sV  = sm + OFF_V;      // [64 kk][256 c], stride 260

    const int t  = threadIdx.x;
    const int tr = t >> 5;        // 0..7  (== warp id)
    const int tc = t & 31;        // 0..31
    const int r0 = tr * 8;
    const int b  = blockIdx.y;
    const int qt = blockIdx.x;

    const float* qbase = gq + (size_t)(b * NSEQ + qt * 64) * DQK;
    const float* kbase = gk + (size_t)b * NSEQ * DQK;
    const float* vbase = gv + (size_t)b * NSEQ * CF;

    // Load + transpose Q tile [64][32] -> sQt[d][r]
    {
        int i = t;
#pragma unroll
        for (int it = 0; it < 2; ++it, i += 256) {
            int r  = i >> 3;
            int c4 = (i & 7) * 4;
            float4 v = *(const float4*)(qbase + r * DQK + c4);
            sQt[(c4 + 0) * S_Q + r] = v.x;
            sQt[(c4 + 1) * S_Q + r] = v.y;
            sQt[(c4 + 2) * S_Q + r] = v.z;
            sQt[(c4 + 3) * S_Q + r] = v.w;
        }
    }

    // O accumulators: f32x2 = (row r0+2rp, row r0+2rp+1); 4 row-pairs x 4 cols x 2 halves
    ull accA[4][4], accB[4][4];
#pragma unroll
    for (int i = 0; i < 4; ++i)
#pragma unroll
        for (int j = 0; j < 4; ++j) { accA[i][j] = 0ULL; accB[i][j] = 0ULL; }
    // row sums, f32x2 row-pairs, accumulated across all tiles
    ull rs2[4] = {0ULL, 0ULL, 0ULL, 0ULL};

    for (int kt = 0; kt < NSEQ / 64; ++kt) {
        __syncthreads();           // previous tile's PV reads (sPt, sV) done

        // K tile [64][32] -> transposed sKt[d][kk]
        {
            int i = t;
#pragma unroll
            for (int it = 0; it < 2; ++it, i += 256) {
                int r  = i >> 3;
                int c4 = (i & 7) * 4;
                float4 v = *(const float4*)(kbase + (size_t)(kt * 64 + r) * DQK + c4);
                sKt[(c4 + 0) * S_K + r] = v.x;
                sKt[(c4 + 1) * S_K + r] = v.y;
                sKt[(c4 + 2) * S_K + r] = v.z;
                sKt[(c4 + 3) * S_K + r] = v.w;
            }
        }
        // V tile [64][256] -> sV row-major
        {
            int i = t;
#pragma unroll
            for (int it = 0; it < 16; ++it, i += 256) {
                int r  = i >> 6;
                int c4 = (i & 63) * 4;
                float4 v = *(const float4*)(vbase + (size_t)(kt * 64 + r) * CF + c4);
                *(float4*)(sV + r * S_V + c4) = v;
            }
        }
        __syncthreads();

        // ---- QK^T: outer product over d; this thread: 8 rows x keys {2tc, 2tc+1}
        ull sacc[4][2];
#pragma unroll
        for (int i = 0; i < 4; ++i) { sacc[i][0] = 0ULL; sacc[i][1] = 0ULL; }

#pragma unroll 8
        for (int d = 0; d < DQK; ++d) {
            const float* qrow = sQt + d * S_Q + r0;
            ull q01 = *(const ull*)(qrow + 0);
            ull q23 = *(const ull*)(qrow + 2);
            ull q45 = *(const ull*)(qrow + 4);
            ull q67 = *(const ull*)(qrow + 6);
            float2 kk2 = *(const float2*)(sKt + d * S_K + 2 * tc);
            ull k0 = pack2(kk2.x);
            ull k1 = pack2(kk2.y);
            fma2(sacc[0][0], q01, k0); fma2(sacc[0][1], q01, k1);
            fma2(sacc[1][0], q23, k0); fma2(sacc[1][1], q23, k1);
            fma2(sacc[2][0], q45, k0); fma2(sacc[2][1], q45, k1);
            fma2(sacc[3][0], q67, k0); fma2(sacc[3][1], q67, k1);
        }

        // exp + rowsum + store transposed P (f32x2 row-pairs)
#pragma unroll
        for (int j = 0; j < 2; ++j) {
            int kk = 2 * tc + j;
            float* pdst = sPt + kk * S_P + r0;
#pragma unroll
            for (int rp = 0; rp < 4; ++rp) {
                float2 s = unpack2(sacc[rp][j]);
                ull pp = pack2f(__expf(s.x), __expf(s.y));
                rs2[rp] = add2(rs2[rp], pp);
                *(ull*)(pdst + 2 * rp) = pp;
            }
        }
        __syncthreads();

        // ---- O += P @ V
#pragma unroll 4
        for (int kk = 0; kk < 64; ++kk) {
            const float* vrow = sV + kk * S_V;
            float4 va = *(const float4*)(vrow + 4 * tc);
            float4 vb = *(const float4*)(vrow + 128 + 4 * tc);
            const ulonglong2* pp = (const ulonglong2*)(sPt + kk * S_P + r0);
            ulonglong2 pA = pp[0];   // rows r0..r0+3
            ulonglong2 pB = pp[1];   // rows r0+4..r0+7
            ull p[4] = {pA.x, pA.y, pB.x, pB.y};
            ull vA0 = pack2(va.x), vA1 = pack2(va.y), vA2 = pack2(va.z), vA3 = pack2(va.w);
            ull vB0 = pack2(vb.x), vB1 = pack2(vb.y), vB2 = pack2(vb.z), vB3 = pack2(vb.w);
#pragma unroll
            for (int rp = 0; rp < 4; ++rp) {
                fma2(accA[rp][0], vA0, p[rp]);
                fma2(accA[rp][1], vA1, p[rp]);
                fma2(accA[rp][2], vA2, p[rp]);
                fma2(accA[rp][3], vA3, p[rp]);
                fma2(accB[rp][0], vB0, p[rp]);
                fma2(accB[rp][1], vB1, p[rp]);
                fma2(accB[rp][2], vB2, p[rp]);
                fma2(accB[rp][3], vB3, p[rp]);
            }
        }
    }

    // Reduce row sums across the 32 lanes of the warp (all lanes share rows)
#pragma unroll
    for (int rp = 0; rp < 4; ++rp) {
#pragma unroll
        for (int m = 16; m > 0; m >>= 1)
            rs2[rp] = add2(rs2[rp], __shfl_xor_sync(0xffffffffu, rs2[rp], m));
    }

    // Normalize + store
#pragma unroll
    for (int rp = 0; rp < 4; ++rp) {
        float2 s = unpack2(rs2[rp]);
        float ix = 1.f / s.x;
        float iy = 1.f / s.y;
        int ra = r0 + 2 * rp;
        float* orowA = gatt + (size_t)(b * NSEQ + qt * 64 + ra) * CF;
        float* orowB = orowA + CF;
        float2 a0 = unpack2(accA[rp][0]);
        float2 a1 = unpack2(accA[rp][1]);
        float2 a2 = unpack2(accA[rp][2]);
        float2 a3 = unpack2(accA[rp][3]);
        float2 b0 = unpack2(accB[rp][0]);
        float2 b1 = unpack2(accB[rp][1]);
        float2 b2 = unpack2(accB[rp][2]);
        float2 b3 = unpack2(accB[rp][3]);
        float4 oa, ob;
        oa.x = a0.x * ix; oa.y = a1.x * ix; oa.z = a2.x * ix; oa.w = a3.x * ix;
        ob.x = b0.x * ix; ob.y = b1.x * ix; ob.z = b2.x * ix; ob.w = b3.x * ix;
        *(float4*)(orowA + 4 * tc)       = oa;
        *(float4*)(orowA + 128 + 4 * tc) = ob;
        oa.x = a0.y * iy; oa.y = a1.y * iy; oa.z = a2.y * iy; oa.w = a3.y * iy;
        ob.x = b0.y * iy; ob.y = b1.y * iy; ob.z = b2.y * iy; ob.w = b3.y * iy;
        *(float4*)(orowB + 4 * tc)       = oa;
        *(float4*)(orowB + 128 + 4 * tc) = ob;
    }
}

// ---------------------------------------------------------------------------
extern "C" void kernel_launch(void* const* d_in, const int* in_sizes, int n_in,
                              void* d_out, int out_size) {
    const float* x  = (const float*)d_in[0];
    const float* Wq = (const float*)d_in[1];
    const float* bq = (const float*)d_in[2];
    const float* Wk = (const float*)d_in[3];
    const float* bk = (const float*)d_in[4];
    const float* Wv = (const float*)d_in[5];
    const float* bv = (const float*)d_in[6];
    const float* Wo = (const float*)d_in[7];
    const float* bo = (const float*)d_in[8];
    float* out = (float*)d_out;

    void *qp, *kp, *vp, *ap;
    cudaGetSymbolAddress(&qp, g_q);
    cudaGetSymbolAddress(&kp, g_k);
    cudaGetSymbolAddress(&vp, g_v);
    cudaGetSymbolAddress(&ap, g_att);
    float* q   = (float*)qp;
    float* k   = (float*)kp;
    float* v   = (float*)vp;
    float* att = (float*)ap;

    cudaFuncSetAttribute(attn_kernel,
                         cudaFuncAttributeMaxDynamicSharedMemorySize,
                         ATTN_SMEM_BYTES);

    dim3 blk(256);
    // QKV projections
    gemm_relu_kernel<0><<<dim3(1, NTOK / 64), blk>>>(x, Wq, bq, nullptr, q, DQK);
    gemm_relu_kernel<0><<<dim3(1, NTOK / 64), blk>>>(x, Wk, bk, nullptr, k, DQK);
    gemm_relu_kernel<0><<<dim3(4, NTOK / 64), blk>>>(x, Wv, bv, nullptr, v, CF);
    // Attention
    attn_kernel<<<dim3(NSEQ / 64, NB), blk, ATTN_SMEM_BYTES>>>(q, k, v, att);
    // Output projection + residual
    gemm_relu_kernel<1><<<dim3(4, NTOK / 64), blk>>>(att, Wo, bo, x, out, CF);
}